// round 2
// baseline (speedup 1.0000x reference)
#include <cuda_runtime.h>

// UnionLayer: out[b, 0:256]   = -1/(-1 + sum_d log(1 - (1-x[b,d]) * W_con[n,d]))
//             out[b, 256:512] = 1 - ( -1/(-1 + sum_d log(1 - x[b,d] * W_dis[n,d])) )
// B=1024, D=512, N=256.
// R2: packed f32x2 math (FFMA2/FMUL2 via PTX), k-major smem (vector LDS),
//     log2-accumulation with single ln2 scale at epilogue.
// Tile: CTA 64x64, 256 threads, thread tile 2M x 8N (as 8 f32x2 pairs).

#define BM 64
#define BN 64
#define BK 32
#define SA 66           // k-major A stride (floats): even for LDS.64 align, 2-way STS conflict
#define SB 68           // k-major B stride: mult of 4 for LDS.128 align
#define DDIM 512
#define NOUT 512
#define NCOLS 256

__device__ __forceinline__ unsigned long long pack2(float a) {
    unsigned long long r;
    asm("mov.b64 %0, {%1, %1};" : "=l"(r) : "f"(a));
    return r;
}
__device__ __forceinline__ unsigned long long fma2(unsigned long long a,
                                                   unsigned long long b,
                                                   unsigned long long c) {
    unsigned long long d;
    asm("fma.rn.f32x2 %0, %1, %2, %3;" : "=l"(d) : "l"(a), "l"(b), "l"(c));
    return d;
}
__device__ __forceinline__ unsigned long long mul2(unsigned long long a,
                                                   unsigned long long b) {
    unsigned long long d;
    asm("mul.rn.f32x2 %0, %1, %2;" : "=l"(d) : "l"(a), "l"(b));
    return d;
}
__device__ __forceinline__ void unpack2(unsigned long long p, float& lo, float& hi) {
    asm("mov.b64 {%0, %1}, %2;" : "=f"(lo), "=f"(hi) : "l"(p));
}

__global__ __launch_bounds__(256) void union_kernel(
    const float* __restrict__ x,
    const float* __restrict__ Wcon,
    const float* __restrict__ Wdis,
    float* __restrict__ out)
{
    __shared__ float Xs[2][BK * SA];   // [k][m], holds -u  (con: x-1, dis: -x)
    __shared__ float Ws[2][BK * SB];   // [k][n]

    const int tid = threadIdx.x;
    const int tx = tid & 7;          // 8 n-octets  -> n = tx*8 .. tx*8+7
    const int ty = tid >> 3;         // 32 m-pairs  -> m = ty*2, ty*2+1
    const int bn0 = blockIdx.x * BN;
    const int bm0 = blockIdx.y * BM;
    const int z   = blockIdx.z;      // 0 = con, 1 = dis
    const float* __restrict__ W = z ? Wdis : Wcon;

    const unsigned long long ONES2 = 0x3F8000003F800000ull;  // (1.0f, 1.0f)

    unsigned long long p[8];         // products: [row(2)][npair(4)]
    float acc[16];                   // log2 sums: [row(2)][n(8)]
#pragma unroll
    for (int i = 0; i < 8; i++) p[i] = ONES2;
#pragma unroll
    for (int i = 0; i < 16; i++) acc[i] = 0.0f;

    float4 xv[2], wv[2];

    // ---- fill chunk 0 (k-major transpose, X negated) ----
#pragma unroll
    for (int i = 0; i < 2; i++) {
        int f = tid + 256 * i;
        int r = f >> 3;              // 0..63 (row m or n)
        int c = (f & 7) << 2;        // 0..28 (k offset)
        xv[i] = *reinterpret_cast<const float4*>(&x[(bm0 + r) * DDIM + c]);
        wv[i] = *reinterpret_cast<const float4*>(&W[(bn0 + r) * DDIM + c]);
    }
#pragma unroll
    for (int i = 0; i < 2; i++) {
        int f = tid + 256 * i;
        int r = f >> 3;
        int c = (f & 7) << 2;
        float4 v = xv[i];
        if (z == 0) { v.x = v.x - 1.0f; v.y = v.y - 1.0f; v.z = v.z - 1.0f; v.w = v.w - 1.0f; }
        else        { v.x = -v.x;       v.y = -v.y;       v.z = -v.z;       v.w = -v.w;       }
        Xs[0][(c + 0) * SA + r] = v.x;
        Xs[0][(c + 1) * SA + r] = v.y;
        Xs[0][(c + 2) * SA + r] = v.z;
        Xs[0][(c + 3) * SA + r] = v.w;
        float4 w4 = wv[i];
        Ws[0][(c + 0) * SB + r] = w4.x;
        Ws[0][(c + 1) * SB + r] = w4.y;
        Ws[0][(c + 2) * SB + r] = w4.z;
        Ws[0][(c + 3) * SB + r] = w4.w;
    }
    __syncthreads();

    const int NCHUNK = DDIM / BK;    // 16

    for (int ck = 0; ck < NCHUNK; ck++) {
        const int buf = ck & 1;

        // prefetch next chunk global -> regs
        if (ck + 1 < NCHUNK) {
            int d0 = (ck + 1) * BK;
#pragma unroll
            for (int i = 0; i < 2; i++) {
                int f = tid + 256 * i;
                int r = f >> 3;
                int c = (f & 7) << 2;
                xv[i] = *reinterpret_cast<const float4*>(&x[(bm0 + r) * DDIM + d0 + c]);
                wv[i] = *reinterpret_cast<const float4*>(&W[(bn0 + r) * DDIM + d0 + c]);
            }
        }

        // ---- compute on buf: packed f32x2 ----
        const float* __restrict__ Xp = Xs[buf];
        const float* __restrict__ Wp = Ws[buf];
#pragma unroll
        for (int k = 0; k < BK; k++) {
            float2 na = *reinterpret_cast<const float2*>(&Xp[k * SA + 2 * ty]);
            unsigned long long a0 = pack2(na.x);
            unsigned long long a1 = pack2(na.y);
            ulonglong2 bA = *reinterpret_cast<const ulonglong2*>(&Wp[k * SB + 8 * tx]);
            ulonglong2 bB = *reinterpret_cast<const ulonglong2*>(&Wp[k * SB + 8 * tx + 4]);
            p[0] = mul2(p[0], fma2(a0, bA.x, ONES2));
            p[1] = mul2(p[1], fma2(a0, bA.y, ONES2));
            p[2] = mul2(p[2], fma2(a0, bB.x, ONES2));
            p[3] = mul2(p[3], fma2(a0, bB.y, ONES2));
            p[4] = mul2(p[4], fma2(a1, bA.x, ONES2));
            p[5] = mul2(p[5], fma2(a1, bA.y, ONES2));
            p[6] = mul2(p[6], fma2(a1, bB.x, ONES2));
            p[7] = mul2(p[7], fma2(a1, bB.y, ONES2));
        }

        // store next chunk to other buffer
        if (ck + 1 < NCHUNK) {
            const int nb = buf ^ 1;
#pragma unroll
            for (int i = 0; i < 2; i++) {
                int f = tid + 256 * i;
                int r = f >> 3;
                int c = (f & 7) << 2;
                float4 v = xv[i];
                if (z == 0) { v.x = v.x - 1.0f; v.y = v.y - 1.0f; v.z = v.z - 1.0f; v.w = v.w - 1.0f; }
                else        { v.x = -v.x;       v.y = -v.y;       v.z = -v.z;       v.w = -v.w;       }
                Xs[nb][(c + 0) * SA + r] = v.x;
                Xs[nb][(c + 1) * SA + r] = v.y;
                Xs[nb][(c + 2) * SA + r] = v.z;
                Xs[nb][(c + 3) * SA + r] = v.w;
                float4 w4 = wv[i];
                Ws[nb][(c + 0) * SB + r] = w4.x;
                Ws[nb][(c + 1) * SB + r] = w4.y;
                Ws[nb][(c + 2) * SB + r] = w4.z;
                Ws[nb][(c + 3) * SB + r] = w4.w;
            }
        }

        // flush products every 2 chunks (64 terms; each term in [0.5,1] so
        // prod >= 0.5^64 ~ 5e-20, safely normal in fp32)
        if (ck & 1) {
#pragma unroll
            for (int i = 0; i < 8; i++) {
                float lo, hi;
                unpack2(p[i], lo, hi);
                acc[i * 2 + 0] += __log2f(lo);
                acc[i * 2 + 1] += __log2f(hi);
            }
#pragma unroll
            for (int i = 0; i < 8; i++) p[i] = ONES2;
        }

        __syncthreads();
    }

    // ---- epilogue: s = ln2 * acc;  y = 1/(1-s);  dis: 1-y ----
    const float LN2 = 0.69314718055994530942f;
#pragma unroll
    for (int r = 0; r < 2; r++) {
        int row = bm0 + ty * 2 + r;
        float v[8];
#pragma unroll
        for (int j = 0; j < 8; j++) {
            // acc layout: p[i] pairs -> acc[2i],acc[2i+1]; row r owns i = r*4..r*4+3
            float s = LN2 * acc[(r * 4 + (j >> 1)) * 2 + (j & 1)];
            float y = 1.0f / (1.0f - s);
            v[j] = z ? (1.0f - y) : y;
        }
        float4 o0 = make_float4(v[0], v[1], v[2], v[3]);
        float4 o1 = make_float4(v[4], v[5], v[6], v[7]);
        float* dst = &out[row * NOUT + z * NCOLS + bn0 + tx * 8];
        *reinterpret_cast<float4*>(dst)     = o0;
        *reinterpret_cast<float4*>(dst + 4) = o1;
    }
}

extern "C" void kernel_launch(void* const* d_in, const int* in_sizes, int n_in,
                              void* d_out, int out_size)
{
    const float* x    = (const float*)d_in[0];
    const float* Wcon = (const float*)d_in[1];
    const float* Wdis = (const float*)d_in[2];
    float* out = (float*)d_out;

    dim3 grid(NCOLS / BN, 1024 / BM, 2);   // (4, 16, 2) = 128 CTAs
    union_kernel<<<grid, 256>>>(x, Wcon, Wdis, out);
}

// round 3
// speedup vs baseline: 1.3549x; 1.3549x over previous
#include <cuda_runtime.h>
#include <cuda_fp16.h>

// UnionLayer: out[b, 0:256]   = -1/(-1 + sum_d log(1 - (1-x[b,d]) * W_con[n,d]))
//             out[b, 256:512] = 1 - ( -1/(-1 + sum_d log(1 - x[b,d] * W_dis[n,d])) )
// B=1024, D=512, N=256.
// R3: fp16x2 mainloop (HFMA2 + HMUL2 at rt2 = 2x fp32 FFMA element throughput).
//   term = 2*(1 - u*w) = hfma2(-2u, w, 2)   in [1,2]  -> no fp16 denorm/overflow
//   fp16 product of 16 terms in [1, 65536)  -> flush into fp32 running product
//   __log2f every 64 terms; subtract 512 doublings once at the end.
// Tile: CTA 64x64, 256 threads, thread tile 4x4, BK=32 double-buffered smem.

#define BM 64
#define BN 64
#define BK 32
#define SA 68           // k-major A stride in halfs (136B: 8B-aligned, bank-rotating)
#define SB 68
#define DDIM 512
#define NOUT 512
#define NCOLS 256

__global__ __launch_bounds__(256) void union_kernel(
    const float* __restrict__ x,
    const float* __restrict__ Wcon,
    const float* __restrict__ Wdis,
    float* __restrict__ out)
{
    __shared__ __half As[2][BK * SA];   // [k][m] holds -2u  (con: 2x-2, dis: -2x)
    __shared__ __half Bs[2][BK * SB];   // [k][n] holds w

    const int tid = threadIdx.x;
    const int tx = tid & 15;         // n = 4*tx .. 4*tx+3
    const int ty = tid >> 4;         // m = 4*ty .. 4*ty+3
    const int bn0 = blockIdx.x * BN;
    const int bm0 = blockIdx.y * BM;
    const int z   = blockIdx.z;      // 0 = con, 1 = dis
    const float* __restrict__ W = z ? Wdis : Wcon;

    const __half2 TWOS = __floats2half2_rn(2.0f, 2.0f);
    const __half2 ONES = __floats2half2_rn(1.0f, 1.0f);

    __half2 p[8];                    // fp16 products: [mm(4)][npair(2)]
    float P[16];                     // fp32 running products
    float acc[16];                   // log2 accumulators
#pragma unroll
    for (int i = 0; i < 8; i++) p[i] = ONES;
#pragma unroll
    for (int i = 0; i < 16; i++) { P[i] = 1.0f; acc[i] = 0.0f; }

    float4 xv[2], wv[2];

    // ---- fill chunk 0 (k-major transpose -> half) ----
#pragma unroll
    for (int i = 0; i < 2; i++) {
        int f = tid + 256 * i;
        int r = f >> 3;              // 0..63
        int c = (f & 7) << 2;        // 0..28
        xv[i] = *reinterpret_cast<const float4*>(&x[(bm0 + r) * DDIM + c]);
        wv[i] = *reinterpret_cast<const float4*>(&W[(bn0 + r) * DDIM + c]);
    }
#pragma unroll
    for (int i = 0; i < 2; i++) {
        int f = tid + 256 * i;
        int r = f >> 3;
        int c = (f & 7) << 2;
        float4 v = xv[i];
        float a0, a1, a2, a3;
        if (z == 0) { a0 = 2.0f*v.x-2.0f; a1 = 2.0f*v.y-2.0f; a2 = 2.0f*v.z-2.0f; a3 = 2.0f*v.w-2.0f; }
        else        { a0 = -2.0f*v.x;     a1 = -2.0f*v.y;     a2 = -2.0f*v.z;     a3 = -2.0f*v.w;     }
        As[0][(c + 0) * SA + r] = __float2half_rn(a0);
        As[0][(c + 1) * SA + r] = __float2half_rn(a1);
        As[0][(c + 2) * SA + r] = __float2half_rn(a2);
        As[0][(c + 3) * SA + r] = __float2half_rn(a3);
        float4 w4 = wv[i];
        Bs[0][(c + 0) * SB + r] = __float2half_rn(w4.x);
        Bs[0][(c + 1) * SB + r] = __float2half_rn(w4.y);
        Bs[0][(c + 2) * SB + r] = __float2half_rn(w4.z);
        Bs[0][(c + 3) * SB + r] = __float2half_rn(w4.w);
    }
    __syncthreads();

    const int NCHUNK = DDIM / BK;    // 16

    for (int ck = 0; ck < NCHUNK; ck++) {
        const int buf = ck & 1;

        // prefetch next chunk global -> regs
        if (ck + 1 < NCHUNK) {
            int d0 = (ck + 1) * BK;
#pragma unroll
            for (int i = 0; i < 2; i++) {
                int f = tid + 256 * i;
                int r = f >> 3;
                int c = (f & 7) << 2;
                xv[i] = *reinterpret_cast<const float4*>(&x[(bm0 + r) * DDIM + d0 + c]);
                wv[i] = *reinterpret_cast<const float4*>(&W[(bn0 + r) * DDIM + d0 + c]);
            }
        }

        // ---- compute on buf: two 16-term groups ----
        const __half* __restrict__ Ap = As[buf];
        const __half* __restrict__ Bp = Bs[buf];
#pragma unroll
        for (int g = 0; g < 2; g++) {
#pragma unroll
            for (int kk = 0; kk < 16; kk++) {
                int k = g * 16 + kk;
                uint2 avu = *reinterpret_cast<const uint2*>(&Ap[k * SA + 4 * ty]);
                uint2 bvu = *reinterpret_cast<const uint2*>(&Bp[k * SB + 4 * tx]);
                __half2 A01 = *reinterpret_cast<__half2*>(&avu.x);
                __half2 A23 = *reinterpret_cast<__half2*>(&avu.y);
                __half2 b01 = *reinterpret_cast<__half2*>(&bvu.x);
                __half2 b23 = *reinterpret_cast<__half2*>(&bvu.y);
                __half2 s0 = __low2half2(A01);
                __half2 s1 = __high2half2(A01);
                __half2 s2 = __low2half2(A23);
                __half2 s3 = __high2half2(A23);
                p[0] = __hmul2(p[0], __hfma2(s0, b01, TWOS));
                p[1] = __hmul2(p[1], __hfma2(s0, b23, TWOS));
                p[2] = __hmul2(p[2], __hfma2(s1, b01, TWOS));
                p[3] = __hmul2(p[3], __hfma2(s1, b23, TWOS));
                p[4] = __hmul2(p[4], __hfma2(s2, b01, TWOS));
                p[5] = __hmul2(p[5], __hfma2(s2, b23, TWOS));
                p[6] = __hmul2(p[6], __hfma2(s3, b01, TWOS));
                p[7] = __hmul2(p[7], __hfma2(s3, b23, TWOS));
            }
            // flush 16-term fp16 products into fp32 running products
#pragma unroll
            for (int i = 0; i < 8; i++) {
                float2 f2 = __half22float2(p[i]);
                P[i * 2 + 0] *= f2.x;
                P[i * 2 + 1] *= f2.y;
                p[i] = ONES;
            }
        }

        // store next chunk to other buffer
        if (ck + 1 < NCHUNK) {
            const int nb = buf ^ 1;
#pragma unroll
            for (int i = 0; i < 2; i++) {
                int f = tid + 256 * i;
                int r = f >> 3;
                int c = (f & 7) << 2;
                float4 v = xv[i];
                float a0, a1, a2, a3;
                if (z == 0) { a0 = 2.0f*v.x-2.0f; a1 = 2.0f*v.y-2.0f; a2 = 2.0f*v.z-2.0f; a3 = 2.0f*v.w-2.0f; }
                else        { a0 = -2.0f*v.x;     a1 = -2.0f*v.y;     a2 = -2.0f*v.z;     a3 = -2.0f*v.w;     }
                As[nb][(c + 0) * SA + r] = __float2half_rn(a0);
                As[nb][(c + 1) * SA + r] = __float2half_rn(a1);
                As[nb][(c + 2) * SA + r] = __float2half_rn(a2);
                As[nb][(c + 3) * SA + r] = __float2half_rn(a3);
                float4 w4 = wv[i];
                Bs[nb][(c + 0) * SB + r] = __float2half_rn(w4.x);
                Bs[nb][(c + 1) * SB + r] = __float2half_rn(w4.y);
                Bs[nb][(c + 2) * SB + r] = __float2half_rn(w4.z);
                Bs[nb][(c + 3) * SB + r] = __float2half_rn(w4.w);
            }
        }

        // every 2 chunks = 64 terms: take log2 of fp32 running product
        // (P = prod of 64 doubled terms, in [1, 2^64] -> fp32 safe)
        if (ck & 1) {
#pragma unroll
            for (int i = 0; i < 16; i++) {
                acc[i] += __log2f(P[i]);
                P[i] = 1.0f;
            }
        }

        __syncthreads();
    }

    // ---- epilogue ----
    // acc = 512 + sum log2(1-t)  (512 doublings over 8 groups of 64)
    // S_ln = ln2 * (acc - 512);  y = 1/(1 - S_ln);  dis: 1 - y
    const float LN2 = 0.69314718055994530942f;
#pragma unroll
    for (int mm = 0; mm < 4; mm++) {
        int row = bm0 + ty * 4 + mm;
        float v[4];
#pragma unroll
        for (int nn = 0; nn < 4; nn++) {
            float s = acc[mm * 4 + nn] - 512.0f;
            float denom = fmaf(-LN2, s, 1.0f);
            float y = 1.0f / denom;
            v[nn] = z ? (1.0f - y) : y;
        }
        float4 o = make_float4(v[0], v[1], v[2], v[3]);
        *reinterpret_cast<float4*>(&out[row * NOUT + z * NCOLS + bn0 + tx * 4]) = o;
    }
}

extern "C" void kernel_launch(void* const* d_in, const int* in_sizes, int n_in,
                              void* d_out, int out_size)
{
    const float* x    = (const float*)d_in[0];
    const float* Wcon = (const float*)d_in[1];
    const float* Wdis = (const float*)d_in[2];
    float* out = (float*)d_out;

    dim3 grid(NCOLS / BN, 1024 / BM, 2);   // (4, 16, 2) = 128 CTAs
    union_kernel<<<grid, 256>>>(x, Wcon, Wdis, out);
}